// round 4
// baseline (speedup 1.0000x reference)
#include <cuda_runtime.h>
#include <cuda_bf16.h>

// Problem constants
#define V_  20000
#define M_  32
#define E_  128
#define H_  4
#define N_  8192
#define L_  64
#define C_  128
#define WPB 4          // words per block in word_embed kernel

// ---------------- device scratch (no allocations allowed) ----------------
__device__ float g_word_embeds[V_ * E_];          // [V,E]
__device__ float g_wt3[E_ * 3 * C_];              // [(e*3+j)*128 + c]
__device__ float g_wt4[E_ * 4 * C_];
__device__ float g_wt5[E_ * 5 * C_];
__device__ float g_wqT[E_ * E_];                  // [e][i] = Wq[i][e]
__device__ float g_wvT[E_ * E_];                  // [e][i] = Wv[i][e]
__device__ float g_woT[E_ * E_];                  // [e][i] = out_w[i][e]
__device__ float g_fcT[3 * C_ * E_];              // [i][c] = fc_w[c][i]

// ---------------- f32x2 helpers ----------------
__device__ __forceinline__ unsigned long long pk2(float x, float y) {
    unsigned long long r;
    asm("mov.b64 %0, {%1,%2};" : "=l"(r) : "f"(x), "f"(y));
    return r;
}
__device__ __forceinline__ void unpk(unsigned long long v, float& x, float& y) {
    asm("mov.b64 {%0,%1}, %2;" : "=f"(x), "=f"(y) : "l"(v));
}
__device__ __forceinline__ unsigned long long ffma2(unsigned long long a,
                                                    unsigned long long b,
                                                    unsigned long long c) {
    unsigned long long d;
    asm("fma.rn.f32x2 %0, %1, %2, %3;" : "=l"(d) : "l"(a), "l"(b), "l"(c));
    return d;
}

// ---------------- prep kernels ----------------
template <int K>
__global__ void transpose_w_kernel(const float* __restrict__ w, float* __restrict__ wt) {
    int i = blockIdx.x * blockDim.x + threadIdx.x;
    const int total = C_ * E_ * K;
    if (i < total) {
        int c = i / (E_ * K);
        int r = i - c * (E_ * K);   // e*K + j
        wt[r * C_ + c] = w[i];
    }
}

// dst[e*128 + i] = src[i*128 + e]   (128x128)
__global__ void transpose128_kernel(const float* __restrict__ src, float* __restrict__ dst) {
    int idx = blockIdx.x * blockDim.x + threadIdx.x;
    if (idx < E_ * E_) {
        int e = idx >> 7, i = idx & 127;
        dst[idx] = src[i * E_ + e];
    }
}

// dst[i*128 + c] = fc_w[c*384 + i]
__global__ void transpose_fc_kernel(const float* __restrict__ src, float* __restrict__ dst) {
    int idx = blockIdx.x * blockDim.x + threadIdx.x;
    if (idx < 3 * C_ * E_) {
        int i = idx >> 7, c = idx & 127;
        dst[idx] = src[c * (3 * C_) + i];
    }
}

// ---------------- word embedding kernel: 4 words per block ----------------
struct WSmem {
    float ctx[WPB][M_][E_ + 1];
    float q[WPB][E_];
    float qh[WPB][E_];
    float g[WPB][H_][E_];
    float ch[WPB][H_][E_];
    float o[WPB][E_];
    float attn[WPB][H_][M_];
    float cb[WPB][H_];
    int   idx[WPB][M_];
    int   len[WPB];
};

__global__ __launch_bounds__(128) void word_embed_kernel(
    const int* __restrict__ word2news, const int* __restrict__ word2news_len,
    const float* __restrict__ table,
    const float* __restrict__ in_w, const float* __restrict__ in_b,
    const float* __restrict__ out_b,
    const float* __restrict__ wqT, const float* __restrict__ wvT,
    const float* __restrict__ woT)
{
    extern __shared__ char smem_raw[];
    WSmem& s = *reinterpret_cast<WSmem*>(smem_raw);

    const int v0 = blockIdx.x * WPB;
    const int tid = threadIdx.x;

    if (tid < WPB * M_) {
        int w = tid >> 5, m = tid & 31;
        s.idx[w][m] = word2news[(v0 + w) * M_ + m];
    }
    if (tid < WPB) s.len[tid] = word2news_len[v0 + tid];
    __syncthreads();

    // gather ctx rows (coalesced per row)
    #pragma unroll
    for (int w = 0; w < WPB; ++w)
        #pragma unroll 4
        for (int m = 0; m < M_; ++m)
            s.ctx[w][m][tid] = table[s.idx[w][m] * E_ + tid];
    __syncthreads();

    // masked mean query
    #pragma unroll
    for (int w = 0; w < WPB; ++w) {
        int len = s.len[w];
        float inv = 1.0f / (float)(len > 0 ? len : 1);
        float a = 0.0f;
        for (int m = 0; m < len; ++m) a += s.ctx[w][m][tid];
        s.q[w][tid] = a * inv;
    }
    __syncthreads();

    // qh = q @ Wq^T + bq      (coalesced wqT, shared across 4 words)
    {
        float acc[WPB];
        #pragma unroll
        for (int w = 0; w < WPB; ++w) acc[w] = 0.0f;
        #pragma unroll 4
        for (int e = 0; e < E_; ++e) {
            float wq = wqT[e * E_ + tid];
            #pragma unroll
            for (int w = 0; w < WPB; ++w) acc[w] += s.q[w][e] * wq;
        }
        float bq = in_b[tid];
        #pragma unroll
        for (int w = 0; w < WPB; ++w) s.qh[w][tid] = acc[w] + bq;
    }
    __syncthreads();

    // g_h[e] = sum_d qh[h*32+d] * Wk[h*32+d][e]   (Wk rows already coalesced)
    #pragma unroll
    for (int h = 0; h < H_; ++h) {
        float acc[WPB];
        #pragma unroll
        for (int w = 0; w < WPB; ++w) acc[w] = 0.0f;
        #pragma unroll 4
        for (int d = 0; d < 32; ++d) {
            float wk = in_w[(E_ + h * 32 + d) * E_ + tid];
            #pragma unroll
            for (int w = 0; w < WPB; ++w) acc[w] += s.qh[w][h * 32 + d] * wk;
        }
        #pragma unroll
        for (int w = 0; w < WPB; ++w) s.g[w][h][tid] = acc[w];
    }
    if (tid < WPB * H_) {
        int w = tid >> 2, h = tid & 3;
        float c = 0.0f;
        for (int d = 0; d < 32; ++d) c += s.qh[w][h * 32 + d] * in_b[E_ + h * 32 + d];
        s.cb[w][h] = c;
    }
    __syncthreads();

    // scores + per-head warp softmax: thread = (h = tid>>5, m = lane)
    {
        const int h = tid >> 5, m = tid & 31;
        #pragma unroll
        for (int w = 0; w < WPB; ++w) {
            float sc = s.cb[w][h];
            #pragma unroll 8
            for (int e = 0; e < E_; ++e) sc += s.ctx[w][m][e] * s.g[w][h][e];
            sc *= 0.17677669529663688f;               // 1/sqrt(32)
            if (m >= s.len[w]) sc = -1e30f;
            float wm = sc;
            #pragma unroll
            for (int o = 16; o; o >>= 1) wm = fmaxf(wm, __shfl_xor_sync(0xFFFFFFFFu, wm, o));
            float p = __expf(sc - wm);
            float ps = p;
            #pragma unroll
            for (int o = 16; o; o >>= 1) ps += __shfl_xor_sync(0xFFFFFFFFu, ps, o);
            s.attn[w][h][m] = p / ps;
        }
    }
    __syncthreads();

    // ch_h[e] = sum_m attn[h,m]*ctx[m][e]
    #pragma unroll
    for (int w = 0; w < WPB; ++w)
        #pragma unroll
        for (int h = 0; h < H_; ++h) {
            float c = 0.0f;
            #pragma unroll 8
            for (int m = 0; m < M_; ++m) c += s.attn[w][h][m] * s.ctx[w][m][tid];
            s.ch[w][h][tid] = c;
        }
    __syncthreads();

    // o[i] = ch_{h(i)} . Wv[i] + bv[i]   (coalesced wvT)
    {
        const int h = tid >> 5;
        float acc[WPB];
        #pragma unroll
        for (int w = 0; w < WPB; ++w) acc[w] = 0.0f;
        #pragma unroll 4
        for (int e = 0; e < E_; ++e) {
            float wv = wvT[e * E_ + tid];
            #pragma unroll
            for (int w = 0; w < WPB; ++w) acc[w] += s.ch[w][h][e] * wv;
        }
        float bv = in_b[2 * E_ + tid];
        #pragma unroll
        for (int w = 0; w < WPB; ++w) s.o[w][tid] = acc[w] + bv;
    }
    __syncthreads();

    // out proj   (coalesced woT)
    {
        float acc[WPB];
        #pragma unroll
        for (int w = 0; w < WPB; ++w) acc[w] = 0.0f;
        #pragma unroll 4
        for (int e = 0; e < E_; ++e) {
            float wo = woT[e * E_ + tid];
            #pragma unroll
            for (int w = 0; w < WPB; ++w) acc[w] += s.o[w][e] * wo;
        }
        float ob = out_b[tid];
        #pragma unroll
        for (int w = 0; w < WPB; ++w)
            g_word_embeds[(v0 + w) * E_ + tid] = (s.len[w] > 0) ? (acc[w] + ob) : 0.0f;
    }
}

// ---------------- conv + maxpool + FC kernel: one block per news item -----
// doc is stored pre-duplicated as (d,d) u64 pairs so packed operands are a
// single broadcast LDS.64 (no pack MOVs in the hot loop).
template <int K>
__device__ __forceinline__ void conv_phase(
    const unsigned long long* __restrict__ wt,  // float2 rows: [(e*K+j)*64 + pair]
    const float* __restrict__ bias,
    const unsigned long long* __restrict__ doc2,   // [L][128] dup-packed
    int half, int pair, int c0,
    float* ph, float* feats_s, int kidx)
{
    constexpr int T = L_ - K + 1;          // 62 / 61 / 60
    const int tlo = half ? (T - 31) : 0;   // halves overlap slightly; max is idempotent

    unsigned long long acc[31];
    #pragma unroll
    for (int t = 0; t < 31; ++t) acc[t] = 0ULL;

    for (int e = 0; e < E_; ++e) {
        unsigned long long w2[K];
        #pragma unroll
        for (int j = 0; j < K; ++j) w2[j] = wt[(e * K + j) * 64 + pair];

        #pragma unroll
        for (int t0 = 0; t0 < 31; t0 += 8) {
            const int CN = (31 - t0 < 8) ? (31 - t0) : 8;
            unsigned long long dpk[8 + K - 1];
            #pragma unroll
            for (int x = 0; x < CN + K - 1; ++x)
                dpk[x] = doc2[(tlo + t0 + x) * E_ + e];   // warp-uniform broadcast
            #pragma unroll
            for (int tt = 0; tt < CN; ++tt) {
                #pragma unroll
                for (int j = 0; j < K; ++j)
                    acc[t0 + tt] = ffma2(dpk[tt + j], w2[j], acc[t0 + tt]);
            }
        }
    }

    float mx = -1e30f, my = -1e30f;
    #pragma unroll
    for (int t = 0; t < 31; ++t) {
        float x, y;
        unpk(acc[t], x, y);
        mx = fmaxf(mx, x);
        my = fmaxf(my, y);
    }
    ph[half * 128 + 2 * pair]     = mx;
    ph[half * 128 + 2 * pair + 1] = my;
    __syncthreads();
    if (half == 0) {
        float a = fmaxf(ph[2 * pair],     ph[128 + 2 * pair]);
        float b = fmaxf(ph[2 * pair + 1], ph[128 + 2 * pair + 1]);
        // max_t relu(y+b) == relu(b + max_t y)
        a = fmaxf(a + bias[c0], 0.0f);
        b = fmaxf(b + bias[c0 + 1], 0.0f);
        feats_s[kidx * C_ + c0]     = a;
        feats_s[kidx * C_ + c0 + 1] = b;
    }
    __syncthreads();
}

__global__ __launch_bounds__(128) void conv_fc_kernel(
    const int* __restrict__ news_words,
    const float* __restrict__ b3, const float* __restrict__ b4, const float* __restrict__ b5,
    const float* __restrict__ fcT, const float* __restrict__ fc_b,
    float* __restrict__ out)
{
    extern __shared__ unsigned long long doc2[];   // [L][128] dup-packed, 64 KB
    __shared__ float ph[256];
    __shared__ float feats_s[3 * C_];
    __shared__ int idx_s[L_];

    const int n = blockIdx.x;
    const int tid = threadIdx.x;

    if (tid < L_) idx_s[tid] = news_words[n * L_ + tid];
    __syncthreads();

    #pragma unroll 4
    for (int l = 0; l < L_; ++l) {
        float v = g_word_embeds[idx_s[l] * E_ + tid];
        doc2[l * E_ + tid] = pk2(v, v);
    }
    __syncthreads();

    const int half = tid >> 6;
    const int pair = tid & 63;
    const int c0 = 2 * pair;

    conv_phase<3>((const unsigned long long*)g_wt3, b3, doc2, half, pair, c0, ph, feats_s, 0);
    conv_phase<4>((const unsigned long long*)g_wt4, b4, doc2, half, pair, c0, ph, feats_s, 1);
    conv_phase<5>((const unsigned long long*)g_wt5, b5, doc2, half, pair, c0, ph, feats_s, 2);

    // FC epilogue: out[n, tid] = fc_b[tid] + feats . fcT[:, tid]   (coalesced)
    float acc = fc_b[tid];
    #pragma unroll 8
    for (int i = 0; i < 3 * C_; ++i) acc += feats_s[i] * fcT[i * E_ + tid];
    out[n * E_ + tid] = acc;
}

// ---------------- launch ----------------
extern "C" void kernel_launch(void* const* d_in, const int* in_sizes, int n_in,
                              void* d_out, int out_size) {
    const int*   word2news     = (const int*)d_in[0];
    const int*   word2news_len = (const int*)d_in[1];
    const int*   news_words    = (const int*)d_in[2];
    const float* table         = (const float*)d_in[3];
    const float* in_w          = (const float*)d_in[4];
    const float* in_b          = (const float*)d_in[5];
    const float* out_w         = (const float*)d_in[6];
    const float* out_b         = (const float*)d_in[7];
    const float* w3            = (const float*)d_in[8];
    const float* b3            = (const float*)d_in[9];
    const float* w4            = (const float*)d_in[10];
    const float* b4            = (const float*)d_in[11];
    const float* w5            = (const float*)d_in[12];
    const float* b5            = (const float*)d_in[13];
    const float* fc_w          = (const float*)d_in[14];
    const float* fc_b          = (const float*)d_in[15];
    float* out = (float*)d_out;

    float *wt3, *wt4, *wt5, *wqT, *wvT, *woT, *fcT;
    cudaGetSymbolAddress((void**)&wt3, g_wt3);
    cudaGetSymbolAddress((void**)&wt4, g_wt4);
    cudaGetSymbolAddress((void**)&wt5, g_wt5);
    cudaGetSymbolAddress((void**)&wqT, g_wqT);
    cudaGetSymbolAddress((void**)&wvT, g_wvT);
    cudaGetSymbolAddress((void**)&woT, g_woT);
    cudaGetSymbolAddress((void**)&fcT, g_fcT);

    // opt-in to >48KB dynamic smem
    static bool attr_done = false;
    cudaFuncSetAttribute(word_embed_kernel,
                         cudaFuncAttributeMaxDynamicSharedMemorySize,
                         (int)sizeof(WSmem));
    cudaFuncSetAttribute(conv_fc_kernel,
                         cudaFuncAttributeMaxDynamicSharedMemorySize,
                         L_ * E_ * 8);
    (void)attr_done;

    // weight transposes (tiny)
    transpose_w_kernel<3><<<(C_*E_*3 + 255) / 256, 256>>>(w3, wt3);
    transpose_w_kernel<4><<<(C_*E_*4 + 255) / 256, 256>>>(w4, wt4);
    transpose_w_kernel<5><<<(C_*E_*5 + 255) / 256, 256>>>(w5, wt5);
    transpose128_kernel<<<(E_*E_ + 255) / 256, 256>>>(in_w, wqT);               // Wq rows 0..127
    transpose128_kernel<<<(E_*E_ + 255) / 256, 256>>>(in_w + 2 * E_ * E_, wvT); // Wv rows 256..383
    transpose128_kernel<<<(E_*E_ + 255) / 256, 256>>>(out_w, woT);
    transpose_fc_kernel<<<(3*C_*E_ + 255) / 256, 256>>>(fc_w, fcT);

    word_embed_kernel<<<V_ / WPB, 128, sizeof(WSmem)>>>(
        word2news, word2news_len, table, in_w, in_b, out_b, wqT, wvT, woT);

    conv_fc_kernel<<<N_, 128, L_ * E_ * 8>>>(news_words, b3, b4, b5, fcT, fc_b, out);
}

// round 5
// speedup vs baseline: 3.2129x; 3.2129x over previous
#include <cuda_runtime.h>
#include <cuda_bf16.h>
#include <cstdint>

// Problem constants
#define V_  20000
#define M_  32
#define E_  128
#define H_  4
#define N_  8192
#define L_  64
#define C_  128
#define WPB 2          // words per block in word_embed kernel

// conv doc tile geometry (unswizzled, bank-conflict-free stride)
#define DSTRIDE 132            // floats per row (132 mod 32 = 4 -> conflict-free ldmatrix-style access)
#define DOCROWS 68             // 64 + 4 pad rows (pads only feed discarded t)
#define DOCN   (DOCROWS * DSTRIDE)

// ---------------- device scratch (no allocations allowed) ----------------
__device__ float g_word_embeds[V_ * E_];          // [V,E]
__device__ float g_wqT[E_ * E_];                  // [e][i] = Wq[i][e]
__device__ float g_wvT[E_ * E_];                  // [e][i] = Wv[i][e]
__device__ float g_woT[E_ * E_];                  // [e][i] = out_w[i][e]
__device__ float g_fcT[3 * C_ * E_];              // [i][c] = fc_w[c][i]
// fragment-packed tf32 conv weights: per kstep s: 8 ntile-pairs x 32 lanes x uint4
// sizes (uint4): K=3: 12288, K=4: 16384, K=5: 20480  -> total 49152 (768 KB)
__device__ uint4 g_wmma[49152];
#define WOFF3 0
#define WOFF4 12288
#define WOFF5 28672

// ---------------- tf32 helpers ----------------
__device__ __forceinline__ uint32_t f2tf32(float x) {
    uint32_t u;
    asm("cvt.rna.tf32.f32 %0, %1;" : "=r"(u) : "f"(x));
    return u;
}

__device__ __forceinline__ void mma_tf32(float* d,
                                         uint32_t a0, uint32_t a1, uint32_t a2, uint32_t a3,
                                         uint32_t b0, uint32_t b1) {
    asm volatile(
        "mma.sync.aligned.m16n8k8.row.col.f32.tf32.tf32.f32 "
        "{%0,%1,%2,%3}, {%4,%5,%6,%7}, {%8,%9}, {%0,%1,%2,%3};"
        : "+f"(d[0]), "+f"(d[1]), "+f"(d[2]), "+f"(d[3])
        : "r"(a0), "r"(a1), "r"(a2), "r"(a3), "r"(b0), "r"(b1));
}

// ---------------- prep kernels ----------------
// dst[e*128 + i] = src[i*128 + e]   (128x128)
__global__ void transpose128_kernel(const float* __restrict__ src, float* __restrict__ dst) {
    int idx = blockIdx.x * blockDim.x + threadIdx.x;
    if (idx < E_ * E_) {
        int e = idx >> 7, i = idx & 127;
        dst[idx] = src[i * E_ + e];
    }
}

// dst[i*128 + c] = fc_w[c*384 + i]
__global__ void transpose_fc_kernel(const float* __restrict__ src, float* __restrict__ dst) {
    int idx = blockIdx.x * blockDim.x + threadIdx.x;
    if (idx < 3 * C_ * E_) {
        int i = idx >> 7, c = idx & 127;
        dst[idx] = src[c * (3 * C_) + i];
    }
}

// Pack conv weights into mma-fragment-linear tf32 layout.
// u32 index = s*1024 + p*128 + lane*4 + q, where
//   s = j*16 + ec (kstep), p = ntile pair, q: {b0 nt=2p, b1 nt=2p, b0 nt=2p+1, b1 nt=2p+1}
//   B frag (k8 x n8, col): b0 -> (k=lane%4, n=lane>>2), b1 -> (k=lane%4+4, n=lane>>2)
//   value = w[c][e][j],  c = nt*8 + (lane>>2),  e = ec*8 + k
template <int K>
__global__ void prep_wmma_kernel(const float* __restrict__ w, int dst_off_u4) {
    int idx = blockIdx.x * blockDim.x + threadIdx.x;
    const int total = K * 16 * 1024;
    if (idx >= total) return;
    int s    = idx >> 10;
    int rem  = idx & 1023;
    int p    = rem >> 7;
    int lane = (rem >> 2) & 31;
    int q    = rem & 3;
    int j  = s >> 4, ec = s & 15;
    int nt = 2 * p + (q >> 1);
    int kk = (lane & 3) + 4 * (q & 1);
    int c  = nt * 8 + (lane >> 2);
    int e  = ec * 8 + kk;
    float v = w[(c * E_ + e) * K + j];
    reinterpret_cast<uint32_t*>(g_wmma)[dst_off_u4 * 4 + idx] = f2tf32(v);
}

// ---------------- word embedding kernel: 2 words per block ----------------
struct WSmem {
    float ctx[WPB][M_][E_ + 1];
    float q[WPB][E_];
    float qh[WPB][E_];
    float g[WPB][H_][E_];
    float ch[WPB][H_][E_];
    float o[WPB][E_];
    float attn[WPB][H_][M_];
    float cb[WPB][H_];
    int   idx[WPB][M_];
    int   len[WPB];
};

__global__ __launch_bounds__(128) void word_embed_kernel(
    const int* __restrict__ word2news, const int* __restrict__ word2news_len,
    const float* __restrict__ table,
    const float* __restrict__ in_w, const float* __restrict__ in_b,
    const float* __restrict__ out_b,
    const float* __restrict__ wqT, const float* __restrict__ wvT,
    const float* __restrict__ woT)
{
    extern __shared__ char smem_raw[];
    WSmem& s = *reinterpret_cast<WSmem*>(smem_raw);

    const int v0 = blockIdx.x * WPB;
    const int tid = threadIdx.x;

    if (tid < WPB * M_) {
        int w = tid >> 5, m = tid & 31;
        s.idx[w][m] = word2news[(v0 + w) * M_ + m];
    }
    if (tid < WPB) s.len[tid] = word2news_len[v0 + tid];
    __syncthreads();

    #pragma unroll
    for (int w = 0; w < WPB; ++w)
        #pragma unroll 4
        for (int m = 0; m < M_; ++m)
            s.ctx[w][m][tid] = table[s.idx[w][m] * E_ + tid];
    __syncthreads();

    // masked mean query
    #pragma unroll
    for (int w = 0; w < WPB; ++w) {
        int len = s.len[w];
        float inv = 1.0f / (float)(len > 0 ? len : 1);
        float a = 0.0f;
        for (int m = 0; m < len; ++m) a += s.ctx[w][m][tid];
        s.q[w][tid] = a * inv;
    }
    __syncthreads();

    // qh = q @ Wq^T + bq  (coalesced wqT, shared across words)
    {
        float acc[WPB];
        #pragma unroll
        for (int w = 0; w < WPB; ++w) acc[w] = 0.0f;
        #pragma unroll 4
        for (int e = 0; e < E_; ++e) {
            float wq = wqT[e * E_ + tid];
            #pragma unroll
            for (int w = 0; w < WPB; ++w) acc[w] += s.q[w][e] * wq;
        }
        float bq = in_b[tid];
        #pragma unroll
        for (int w = 0; w < WPB; ++w) s.qh[w][tid] = acc[w] + bq;
    }
    __syncthreads();

    // g_h[e] = sum_d qh[h*32+d] * Wk[h*32+d][e]
    #pragma unroll
    for (int h = 0; h < H_; ++h) {
        float acc[WPB];
        #pragma unroll
        for (int w = 0; w < WPB; ++w) acc[w] = 0.0f;
        #pragma unroll 4
        for (int d = 0; d < 32; ++d) {
            float wk = in_w[(E_ + h * 32 + d) * E_ + tid];
            #pragma unroll
            for (int w = 0; w < WPB; ++w) acc[w] += s.qh[w][h * 32 + d] * wk;
        }
        #pragma unroll
        for (int w = 0; w < WPB; ++w) s.g[w][h][tid] = acc[w];
    }
    if (tid < WPB * H_) {
        int w = tid >> 2, h = tid & 3;
        float c = 0.0f;
        for (int d = 0; d < 32; ++d) c += s.qh[w][h * 32 + d] * in_b[E_ + h * 32 + d];
        s.cb[w][h] = c;
    }
    __syncthreads();

    // scores + per-head warp softmax
    {
        const int h = tid >> 5, m = tid & 31;
        #pragma unroll
        for (int w = 0; w < WPB; ++w) {
            float sc = s.cb[w][h];
            #pragma unroll 8
            for (int e = 0; e < E_; ++e) sc += s.ctx[w][m][e] * s.g[w][h][e];
            sc *= 0.17677669529663688f;               // 1/sqrt(32)
            if (m >= s.len[w]) sc = -1e30f;
            float wm = sc;
            #pragma unroll
            for (int o = 16; o; o >>= 1) wm = fmaxf(wm, __shfl_xor_sync(0xFFFFFFFFu, wm, o));
            float p = __expf(sc - wm);
            float ps = p;
            #pragma unroll
            for (int o = 16; o; o >>= 1) ps += __shfl_xor_sync(0xFFFFFFFFu, ps, o);
            s.attn[w][h][m] = p / ps;
        }
    }
    __syncthreads();

    // ch_h[e] = sum_m attn[h,m]*ctx[m][e]
    #pragma unroll
    for (int w = 0; w < WPB; ++w)
        #pragma unroll
        for (int h = 0; h < H_; ++h) {
            float c = 0.0f;
            #pragma unroll 8
            for (int m = 0; m < M_; ++m) c += s.attn[w][h][m] * s.ctx[w][m][tid];
            s.ch[w][h][tid] = c;
        }
    __syncthreads();

    // o[i] = ch_{h(i)} . Wv[i] + bv[i]
    {
        const int h = tid >> 5;
        float acc[WPB];
        #pragma unroll
        for (int w = 0; w < WPB; ++w) acc[w] = 0.0f;
        #pragma unroll 4
        for (int e = 0; e < E_; ++e) {
            float wv = wvT[e * E_ + tid];
            #pragma unroll
            for (int w = 0; w < WPB; ++w) acc[w] += s.ch[w][h][e] * wv;
        }
        float bv = in_b[2 * E_ + tid];
        #pragma unroll
        for (int w = 0; w < WPB; ++w) s.o[w][tid] = acc[w] + bv;
    }
    __syncthreads();

    // out proj
    {
        float acc[WPB];
        #pragma unroll
        for (int w = 0; w < WPB; ++w) acc[w] = 0.0f;
        #pragma unroll 4
        for (int e = 0; e < E_; ++e) {
            float wo = woT[e * E_ + tid];
            #pragma unroll
            for (int w = 0; w < WPB; ++w) acc[w] += s.o[w][e] * wo;
        }
        float ob = out_b[tid];
        #pragma unroll
        for (int w = 0; w < WPB; ++w)
            g_word_embeds[(v0 + w) * E_ + tid] = (s.len[w] > 0) ? (acc[w] + ob) : 0.0f;
    }
}

// ---------------- conv (tf32 mma) + maxpool + FC: 2 news per block ----------
// Warp w: news = w>>1, covers stacked t rows (w&1)*32 .. +31 (2 mtiles of 16),
// all 128 channels (16 ntiles of 8). D[t][c] += A(t,·)B(·,c) per (j, e-chunk).
template <int K>
__device__ __forceinline__ void conv_mma_phase(
    const uint4* __restrict__ B, const float* __restrict__ bias,
    const uint32_t* __restrict__ doc, float* pp, float* feats, int kidx, int tid)
{
    const int lane = tid & 31, warp = tid >> 5;
    const int news = warp >> 1;
    const int tb = (warp & 1) * 32;
    const uint32_t* dbase = doc + news * DOCN;

    float d[2][16][4];
    #pragma unroll
    for (int mt = 0; mt < 2; ++mt)
        #pragma unroll
        for (int nt = 0; nt < 16; ++nt)
            #pragma unroll
            for (int k = 0; k < 4; ++k) d[mt][nt][k] = 0.0f;

    for (int s = 0; s < K * 16; ++s) {
        const int j = s >> 4, ec = s & 15;
        const uint32_t* dp = dbase + (tb + j + (lane >> 2)) * DSTRIDE + ec * 8 + (lane & 3);
        uint32_t a[2][4];
        #pragma unroll
        for (int mt = 0; mt < 2; ++mt) {
            a[mt][0] = dp[(16 * mt) * DSTRIDE];
            a[mt][1] = dp[(16 * mt + 8) * DSTRIDE];
            a[mt][2] = dp[(16 * mt) * DSTRIDE + 4];
            a[mt][3] = dp[(16 * mt + 8) * DSTRIDE + 4];
        }
        const uint4* bp = B + s * 256 + lane;
        #pragma unroll
        for (int p = 0; p < 8; ++p) {
            uint4 bb = bp[p * 32];
            mma_tf32(d[0][2 * p],     a[0][0], a[0][1], a[0][2], a[0][3], bb.x, bb.y);
            mma_tf32(d[1][2 * p],     a[1][0], a[1][1], a[1][2], a[1][3], bb.x, bb.y);
            mma_tf32(d[0][2 * p + 1], a[0][0], a[0][1], a[0][2], a[0][3], bb.z, bb.w);
            mma_tf32(d[1][2 * p + 1], a[1][0], a[1][1], a[1][2], a[1][3], bb.z, bb.w);
        }
    }

    // max over valid t within warp, then across lane-groups
    constexpr int T = L_ - K + 1;
    #pragma unroll
    for (int nt = 0; nt < 16; ++nt)
        #pragma unroll
        for (int r = 0; r < 2; ++r) {
            float m = -1e30f;
            #pragma unroll
            for (int mt = 0; mt < 2; ++mt)
                #pragma unroll
                for (int rr = 0; rr < 2; ++rr) {
                    int tl = tb + 16 * mt + (lane >> 2) + 8 * rr;
                    if (tl < T) m = fmaxf(m, d[mt][nt][2 * rr + r]);
                }
            m = fmaxf(m, __shfl_xor_sync(0xFFFFFFFFu, m, 4));
            m = fmaxf(m, __shfl_xor_sync(0xFFFFFFFFu, m, 8));
            m = fmaxf(m, __shfl_xor_sync(0xFFFFFFFFu, m, 16));
            if (lane < 4) pp[warp * 128 + nt * 8 + 2 * lane + r] = m;
        }
    __syncthreads();
    {
        int c = tid;
        #pragma unroll
        for (int b = 0; b < 2; ++b) {
            float v = fmaxf(pp[(2 * b) * 128 + c], pp[(2 * b + 1) * 128 + c]);
            feats[b * 384 + kidx * 128 + c] = fmaxf(v + bias[c], 0.0f);
        }
    }
    __syncthreads();
}

__global__ __launch_bounds__(128) void conv_mma_kernel(
    const int* __restrict__ news_words,
    const float* __restrict__ b3, const float* __restrict__ b4, const float* __restrict__ b5,
    const float* __restrict__ fcT, const float* __restrict__ fc_b,
    float* __restrict__ out)
{
    extern __shared__ uint32_t cs[];
    uint32_t* doc   = cs;                               // 2*DOCN u32 (tf32 bits)
    float*    pp    = (float*)(cs + 2 * DOCN);          // 4*128
    float*    feats = pp + 512;                         // 2*384
    int*      idx2  = (int*)(feats + 768);              // 128

    const int n0 = blockIdx.x * 2;
    const int tid = threadIdx.x;

    idx2[tid] = news_words[n0 * L_ + tid];              // 2*64 = 128 indices
    __syncthreads();

    #pragma unroll
    for (int b = 0; b < 2; ++b)
        #pragma unroll 4
        for (int l = 0; l < L_; ++l) {
            float v = g_word_embeds[idx2[b * L_ + l] * E_ + tid];
            doc[b * DOCN + l * DSTRIDE + tid] = f2tf32(v);
        }
    __syncthreads();

    conv_mma_phase<3>(g_wmma + WOFF3, b3, doc, pp, feats, 0, tid);
    conv_mma_phase<4>(g_wmma + WOFF4, b4, doc, pp, feats, 1, tid);
    conv_mma_phase<5>(g_wmma + WOFF5, b5, doc, pp, feats, 2, tid);

    // FC epilogue: out[n, i] = fc_b[i] + feats . fcT[:, i]
    const int i = tid;
    #pragma unroll
    for (int b = 0; b < 2; ++b) {
        float acc = fc_b[i];
        #pragma unroll 8
        for (int k = 0; k < 3 * C_; ++k) acc += feats[b * 384 + k] * fcT[k * E_ + i];
        out[(n0 + b) * E_ + i] = acc;
    }
}

// ---------------- launch ----------------
extern "C" void kernel_launch(void* const* d_in, const int* in_sizes, int n_in,
                              void* d_out, int out_size) {
    const int*   word2news     = (const int*)d_in[0];
    const int*   word2news_len = (const int*)d_in[1];
    const int*   news_words    = (const int*)d_in[2];
    const float* table         = (const float*)d_in[3];
    const float* in_w          = (const float*)d_in[4];
    const float* in_b          = (const float*)d_in[5];
    const float* out_w         = (const float*)d_in[6];
    const float* out_b         = (const float*)d_in[7];
    const float* w3            = (const float*)d_in[8];
    const float* b3            = (const float*)d_in[9];
    const float* w4            = (const float*)d_in[10];
    const float* b4            = (const float*)d_in[11];
    const float* w5            = (const float*)d_in[12];
    const float* b5            = (const float*)d_in[13];
    const float* fc_w          = (const float*)d_in[14];
    const float* fc_b          = (const float*)d_in[15];
    float* out = (float*)d_out;

    float *wqT, *wvT, *woT, *fcT;
    cudaGetSymbolAddress((void**)&wqT, g_wqT);
    cudaGetSymbolAddress((void**)&wvT, g_wvT);
    cudaGetSymbolAddress((void**)&woT, g_woT);
    cudaGetSymbolAddress((void**)&fcT, g_fcT);

    const int word_smem = (int)sizeof(WSmem);
    const int conv_smem = (2 * DOCN + 512 + 768 + 128) * 4;
    cudaFuncSetAttribute(word_embed_kernel,
                         cudaFuncAttributeMaxDynamicSharedMemorySize, word_smem);
    cudaFuncSetAttribute(conv_mma_kernel,
                         cudaFuncAttributeMaxDynamicSharedMemorySize, conv_smem);

    // prep: transposes + fragment-packed conv weights (all tiny)
    transpose128_kernel<<<(E_*E_ + 255) / 256, 256>>>(in_w, wqT);
    transpose128_kernel<<<(E_*E_ + 255) / 256, 256>>>(in_w + 2 * E_ * E_, wvT);
    transpose128_kernel<<<(E_*E_ + 255) / 256, 256>>>(out_w, woT);
    transpose_fc_kernel<<<(3*C_*E_ + 255) / 256, 256>>>(fc_w, fcT);
    prep_wmma_kernel<3><<<(3*16*1024 + 255) / 256, 256>>>(w3, WOFF3);
    prep_wmma_kernel<4><<<(4*16*1024 + 255) / 256, 256>>>(w4, WOFF4);
    prep_wmma_kernel<5><<<(5*16*1024 + 255) / 256, 256>>>(w5, WOFF5);

    word_embed_kernel<<<V_ / WPB, 128, word_smem>>>(
        word2news, word2news_len, table, in_w, in_b, out_b, wqT, wvT, woT);

    conv_mma_kernel<<<N_ / 2, 128, conv_smem>>>(news_words, b3, b4, b5, fcT, fc_b, out);
}